// round 12
// baseline (speedup 1.0000x reference)
#include <cuda_runtime.h>

// LDE_58961311040249 — R12: R9 base (tcgen05 unavailable: harness targets
// compute_103 virtual arch). GEMM2 i-paired (natural x pairs, fewer dups),
// partE flipped to [b][c][k][i] -> phase2 reads/writes fully coalesced.
//   d[b,t,k]  = s[k] * (||x_bt||^2 - 2 x_bt·m_k + ||m_k||^2)
//   w         = softmax_k(d)
//   out[b,k,i]= (sum_t w*x_i)/T - m[i,k]*(sum_t w)/T

#define B_      16
#define T_      2048
#define NIN     128
#define NOUT    64
#define CHUNKS  16
#define TILE_T  (T_ / CHUNKS)   // 128

#define XS_LD   132   // x row stride (floats), mult of 4 -> 16B-aligned rows
#define WS_LD   68    // w row stride (floats)

__device__ float g_partE [B_ * CHUNKS * NOUT * NIN];  // [b][c][k][i], 8 MB
__device__ float g_partWS[B_ * CHUNKS * NOUT];

typedef unsigned long long u64;

__device__ __forceinline__ void lds_v2u(u64 &p0, u64 &p1, unsigned off) {
    asm volatile("ld.shared.v2.u64 {%0,%1}, [%2];" : "=l"(p0), "=l"(p1) : "r"(off));
}
__device__ __forceinline__ float2 lds_v2f(unsigned off) {
    float2 r;
    asm volatile("ld.shared.v2.f32 {%0,%1}, [%2];" : "=f"(r.x), "=f"(r.y) : "r"(off));
    return r;
}
__device__ __forceinline__ float lds_f(unsigned off) {
    float r; asm volatile("ld.shared.f32 %0, [%1];" : "=f"(r) : "r"(off)); return r;
}
__device__ __forceinline__ void fma2(u64 &d, u64 a, u64 b) {
    asm("fma.rn.f32x2 %0, %1, %2, %0;" : "+l"(d) : "l"(a), "l"(b));
}
__device__ __forceinline__ u64 dup2(float v) {
    u64 d; asm("mov.b64 %0, {%1,%1};" : "=l"(d) : "f"(v)); return d;
}
__device__ __forceinline__ float2 unpack2(u64 v) {
    float2 r; asm("mov.b64 {%0,%1}, %2;" : "=f"(r.x), "=f"(r.y) : "l"(v)); return r;
}

__global__ void lde_dummy() {}

__global__ __launch_bounds__(256, 2) void lde_phase1(
    const float* __restrict__ x,
    const float* __restrict__ s,
    const float* __restrict__ m)
{
    extern __shared__ float smf[];
    float* x_s = smf;                         // 128*132 f (67584 B)
    float* m_s = x_s + TILE_T * XS_LD;        // union: m[i][k] dense (8192 f)
    float* w_s = m_s;                         //        w[r][k] WS_LD  (8704 f)
    float* xn  = m_s + TILE_T * WS_LD;        // 128
    float* mn  = xn + TILE_T;                 // 64
    float* s_s = mn + NOUT;                   // 64

    const int tid = threadIdx.x;
    const int c   = blockIdx.x;
    const int b   = blockIdx.y;
    const float* xg = x + ((size_t)b * T_ + (size_t)c * TILE_T) * NIN;

    // ---- load M natural [i][k]: dense float4 copy ----
    for (int e = tid; e < (NIN * NOUT) / 4; e += 256) {
        float4 v = reinterpret_cast<const float4*>(m)[e];
        reinterpret_cast<float4*>(m_s)[e] = v;
    }
    // ---- load X tile (float4 in, float4 out: XS_LD mult of 4) ----
    for (int e = tid; e < TILE_T * (NIN / 4); e += 256) {
        int r = e >> 5, q = e & 31;
        float4 v = reinterpret_cast<const float4*>(xg + r * NIN)[q];
        *reinterpret_cast<float4*>(x_s + r * XS_LD + q * 4) = v;
    }
    __syncthreads();

    const unsigned xb = (unsigned)__cvta_generic_to_shared(x_s);
    const unsigned mb = (unsigned)__cvta_generic_to_shared(m_s);
    const unsigned wb = (unsigned)__cvta_generic_to_shared(w_s);

    // ---- norms in parallel: tids 0-127 xn, 128-191 mn, 192-255 s_s ----
    if (tid < TILE_T) {
        const unsigned base = xb + (unsigned)(tid * XS_LD) * 4u;
        float a = 0.f;
        #pragma unroll 8
        for (int i = 0; i < NIN; i += 2) {
            float2 v = lds_v2f(base + (unsigned)i * 4u);
            a += v.x * v.x + v.y * v.y;
        }
        xn[tid] = a;
    } else if (tid < 192) {
        const int k = tid - 128;
        float a = 0.f;
        #pragma unroll 8
        for (int i = 0; i < NIN; i++) {
            float v = lds_f(mb + (unsigned)(i * NOUT + k) * 4u);
            a += v * v;
        }
        mn[k] = a;
    } else {
        s_s[tid - 192] = s[tid - 192];
    }
    __syncthreads();

    // ======== GEMM1: dot[r][k], tile 8r x 4k per thread (k-paired) ========
    const int kb = tid & 15;          // k = 4*kb .. 4*kb+3
    const int rb = tid >> 4;          // 0..15
    const int r0 = rb * 8;
    const int k0 = kb * 4;
    u64 acc[8][2];
    #pragma unroll
    for (int u = 0; u < 8; u++) { acc[u][0] = 0ull; acc[u][1] = 0ull; }

    const unsigned ax = xb + (unsigned)(r0 * XS_LD) * 4u;
    const unsigned bx = mb + (unsigned)k0 * 4u;

    #pragma unroll 2
    for (int i = 0; i < NIN; i += 2) {
        float2 av[8];
        #pragma unroll
        for (int u = 0; u < 8; u++)
            av[u] = lds_v2f(ax + (unsigned)(u * XS_LD + i) * 4u);
        u64 bp0, bp1, cp0, cp1;
        lds_v2u(bp0, bp1, bx + (unsigned)(i * NOUT) * 4u);
        lds_v2u(cp0, cp1, bx + (unsigned)((i + 1) * NOUT) * 4u);
        #pragma unroll
        for (int u = 0; u < 8; u++) {
            u64 a0 = dup2(av[u].x), a1 = dup2(av[u].y);
            fma2(acc[u][0], a0, bp0);
            fma2(acc[u][1], a0, bp1);
            fma2(acc[u][0], a1, cp0);
            fma2(acc[u][1], a1, cp1);
        }
    }

    // All GEMM1 reads of m_s must complete before w_s (alias) is written.
    __syncthreads();

    // ======== d-transform + softmax over k (16-lane xor shuffles) ========
    float mnl[4], ssl[4];
    #pragma unroll
    for (int q = 0; q < 4; q++) { mnl[q] = mn[k0 + q]; ssl[q] = s_s[k0 + q]; }

    #pragma unroll
    for (int u = 0; u < 8; u++) {
        const int r = r0 + u;
        const float xr = xn[r];
        float dv[4];
        float2 p0 = unpack2(acc[u][0]);
        float2 p1 = unpack2(acc[u][1]);
        dv[0] = ssl[0] * (xr - 2.f * p0.x + mnl[0]);
        dv[1] = ssl[1] * (xr - 2.f * p0.y + mnl[1]);
        dv[2] = ssl[2] * (xr - 2.f * p1.x + mnl[2]);
        dv[3] = ssl[3] * (xr - 2.f * p1.y + mnl[3]);

        float mx = fmaxf(fmaxf(dv[0], dv[1]), fmaxf(dv[2], dv[3]));
        #pragma unroll
        for (int off = 1; off < 16; off <<= 1)
            mx = fmaxf(mx, __shfl_xor_sync(0xffffffffu, mx, off));

        float ev[4], sum = 0.f;
        #pragma unroll
        for (int q = 0; q < 4; q++) { ev[q] = __expf(dv[q] - mx); sum += ev[q]; }
        #pragma unroll
        for (int off = 1; off < 16; off <<= 1)
            sum += __shfl_xor_sync(0xffffffffu, sum, off);

        const float inv = 1.f / sum;
        *reinterpret_cast<float4*>(w_s + r * WS_LD + k0) =
            make_float4(ev[0]*inv, ev[1]*inv, ev[2]*inv, ev[3]*inv);
    }
    __syncthreads();

    // ======== GEMM2: E[k][i] = sum_r w[r][k]*x[r][i], i-paired accs ========
    const int ib = tid >> 4;          // i = ib*8 .. ib*8+7
    const int i0 = ib * 8;
    u64 acc2[4][4];                   // [kq][p]; pair = (i0+2p, i0+2p+1)
    #pragma unroll
    for (int kq = 0; kq < 4; kq++)
        #pragma unroll
        for (int p = 0; p < 4; p++) acc2[kq][p] = 0ull;

    const unsigned xi = xb + (unsigned)i0 * 4u;
    const float* wrow = w_s + k0;

    #pragma unroll 4
    for (int r = 0; r < TILE_T; r++) {
        float4 wv = *reinterpret_cast<const float4*>(wrow + r * WS_LD);
        u64 xp[4];
        lds_v2u(xp[0], xp[1], xi + (unsigned)(r * XS_LD) * 4u);
        lds_v2u(xp[2], xp[3], xi + (unsigned)(r * XS_LD) * 4u + 16u);
        u64 w0 = dup2(wv.x), w1 = dup2(wv.y), w2 = dup2(wv.z), w3 = dup2(wv.w);
        #pragma unroll
        for (int p = 0; p < 4; p++) {
            fma2(acc2[0][p], w0, xp[p]);
            fma2(acc2[1][p], w1, xp[p]);
            fma2(acc2[2][p], w2, xp[p]);
            fma2(acc2[3][p], w3, xp[p]);
        }
    }

    // partE [b][c][k][i]: 16B stores, i-contiguous
    float* pe = g_partE + (size_t)(b * CHUNKS + c) * NOUT * NIN;
    #pragma unroll
    for (int kq = 0; kq < 4; kq++) {
        ulonglong2 o0; o0.x = acc2[kq][0]; o0.y = acc2[kq][1];
        ulonglong2 o1; o1.x = acc2[kq][2]; o1.y = acc2[kq][3];
        *reinterpret_cast<ulonglong2*>(pe + (k0 + kq) * NIN + i0)     = o0;
        *reinterpret_cast<ulonglong2*>(pe + (k0 + kq) * NIN + i0 + 4) = o1;
    }

    // ---- per-chunk wsum[k] ----
    if (tid < NOUT) {
        float a = 0.f;
        #pragma unroll 8
        for (int r = 0; r < TILE_T; r++) a += w_s[r * WS_LD + tid];
        g_partWS[(b * CHUNKS + c) * NOUT + tid] = a;
    }
}

__global__ __launch_bounds__(256) void lde_phase2(
    const float* __restrict__ m, float* __restrict__ out)
{
    const int g = blockIdx.x * 256 + threadIdx.x;   // 65536 = B*NOUT*(NIN/2)
    const int b = g >> 12;
    const int k = (g >> 6) & 63;
    const int p = g & 63;                           // i pair: i = 2p, 2p+1

    float2 se = make_float2(0.f, 0.f);
    float  sw = 0.f;
    #pragma unroll
    for (int c = 0; c < CHUNKS; c++) {
        const float2 v = *reinterpret_cast<const float2*>(
            g_partE + ((size_t)((b * CHUNKS + c) * NOUT + k)) * NIN + 2 * p);
        se.x += v.x; se.y += v.y;
        sw   += g_partWS[(b * CHUNKS + c) * NOUT + k];
    }
    const float m0 = m[(2 * p) * NOUT + k];
    const float m1 = m[(2 * p + 1) * NOUT + k];
    const float inv_t = 1.f / (float)T_;
    float2 o;
    o.x = (se.x - m0 * sw) * inv_t;
    o.y = (se.y - m1 * sw) * inv_t;
    *reinterpret_cast<float2*>(out + ((size_t)b * NOUT + k) * NIN + 2 * p) = o;
}

extern "C" void kernel_launch(void* const* d_in, const int* in_sizes, int n_in,
                              void* d_out, int out_size)
{
    const float* x = nullptr; const float* s = nullptr; const float* m = nullptr;
    for (int i = 0; i < n_in; i++) {
        if      (in_sizes[i] == B_ * T_ * NIN) x = (const float*)d_in[i];
        else if (in_sizes[i] == NOUT)          s = (const float*)d_in[i];
        else if (in_sizes[i] == NIN * NOUT)    m = (const float*)d_in[i];
    }
    float* out = (float*)d_out;

    const int smem_bytes =
        (TILE_T * XS_LD + TILE_T * WS_LD + TILE_T + 2 * NOUT)
        * (int)sizeof(float);   // ~104 KB

    cudaFuncSetAttribute(lde_phase1,
                         cudaFuncAttributeMaxDynamicSharedMemorySize, smem_bytes);

    // 3 launches/call: with the +2 stream offset, ncu -s 5 captures phase1.
    lde_phase1<<<dim3(CHUNKS, B_), 256, smem_bytes>>>(x, s, m);
    lde_phase2<<<(B_ * NOUT * NIN / 2) / 256, 256>>>(m, out);
    lde_dummy<<<1, 32>>>();
}

// round 13
// speedup vs baseline: 1.0528x; 1.0528x over previous
#include <cuda_runtime.h>

// LDE_58961311040249 — R13: R12 base minus the dummy launch (−1.3us wall),
// deeper unrolls (GEMM1 x4, GEMM2 x8) for scheduler slack against
// short-scoreboard stalls (profile: issue 32%, fma 33%, L1 42% — stall-bound).
//   d[b,t,k]  = s[k] * (||x_bt||^2 - 2 x_bt·m_k + ||m_k||^2)
//   w         = softmax_k(d)
//   out[b,k,i]= (sum_t w*x_i)/T - m[i,k]*(sum_t w)/T

#define B_      16
#define T_      2048
#define NIN     128
#define NOUT    64
#define CHUNKS  16
#define TILE_T  (T_ / CHUNKS)   // 128

#define XS_LD   132   // x row stride (floats), mult of 4 -> 16B-aligned rows
#define WS_LD   68    // w row stride (floats)

__device__ float g_partE [B_ * CHUNKS * NOUT * NIN];  // [b][c][k][i], 8 MB
__device__ float g_partWS[B_ * CHUNKS * NOUT];

typedef unsigned long long u64;

__device__ __forceinline__ void lds_v2u(u64 &p0, u64 &p1, unsigned off) {
    asm volatile("ld.shared.v2.u64 {%0,%1}, [%2];" : "=l"(p0), "=l"(p1) : "r"(off));
}
__device__ __forceinline__ float2 lds_v2f(unsigned off) {
    float2 r;
    asm volatile("ld.shared.v2.f32 {%0,%1}, [%2];" : "=f"(r.x), "=f"(r.y) : "r"(off));
    return r;
}
__device__ __forceinline__ float lds_f(unsigned off) {
    float r; asm volatile("ld.shared.f32 %0, [%1];" : "=f"(r) : "r"(off)); return r;
}
__device__ __forceinline__ void fma2(u64 &d, u64 a, u64 b) {
    asm("fma.rn.f32x2 %0, %1, %2, %0;" : "+l"(d) : "l"(a), "l"(b));
}
__device__ __forceinline__ u64 dup2(float v) {
    u64 d; asm("mov.b64 %0, {%1,%1};" : "=l"(d) : "f"(v)); return d;
}
__device__ __forceinline__ float2 unpack2(u64 v) {
    float2 r; asm("mov.b64 {%0,%1}, %2;" : "=f"(r.x), "=f"(r.y) : "l"(v)); return r;
}

__global__ __launch_bounds__(256, 2) void lde_phase1(
    const float* __restrict__ x,
    const float* __restrict__ s,
    const float* __restrict__ m)
{
    extern __shared__ float smf[];
    float* x_s = smf;                         // 128*132 f (67584 B)
    float* m_s = x_s + TILE_T * XS_LD;        // union: m[i][k] dense (8192 f)
    float* w_s = m_s;                         //        w[r][k] WS_LD  (8704 f)
    float* xn  = m_s + TILE_T * WS_LD;        // 128
    float* mn  = xn + TILE_T;                 // 64
    float* s_s = mn + NOUT;                   // 64

    const int tid = threadIdx.x;
    const int c   = blockIdx.x;
    const int b   = blockIdx.y;
    const float* xg = x + ((size_t)b * T_ + (size_t)c * TILE_T) * NIN;

    // ---- load M natural [i][k]: dense float4 copy ----
    for (int e = tid; e < (NIN * NOUT) / 4; e += 256) {
        float4 v = reinterpret_cast<const float4*>(m)[e];
        reinterpret_cast<float4*>(m_s)[e] = v;
    }
    // ---- load X tile (float4 in, float4 out) ----
    for (int e = tid; e < TILE_T * (NIN / 4); e += 256) {
        int r = e >> 5, q = e & 31;
        float4 v = reinterpret_cast<const float4*>(xg + r * NIN)[q];
        *reinterpret_cast<float4*>(x_s + r * XS_LD + q * 4) = v;
    }
    __syncthreads();

    const unsigned xb = (unsigned)__cvta_generic_to_shared(x_s);
    const unsigned mb = (unsigned)__cvta_generic_to_shared(m_s);
    const unsigned wb = (unsigned)__cvta_generic_to_shared(w_s);

    // ---- norms in parallel: tids 0-127 xn, 128-191 mn, 192-255 s_s ----
    if (tid < TILE_T) {
        const unsigned base = xb + (unsigned)(tid * XS_LD) * 4u;
        float a = 0.f;
        #pragma unroll 8
        for (int i = 0; i < NIN; i += 2) {
            float2 v = lds_v2f(base + (unsigned)i * 4u);
            a += v.x * v.x + v.y * v.y;
        }
        xn[tid] = a;
    } else if (tid < 192) {
        const int k = tid - 128;
        float a = 0.f;
        #pragma unroll 8
        for (int i = 0; i < NIN; i++) {
            float v = lds_f(mb + (unsigned)(i * NOUT + k) * 4u);
            a += v * v;
        }
        mn[k] = a;
    } else {
        s_s[tid - 192] = s[tid - 192];
    }
    __syncthreads();

    // ======== GEMM1: dot[r][k], tile 8r x 4k per thread (k-paired) ========
    const int kb = tid & 15;          // k = 4*kb .. 4*kb+3
    const int rb = tid >> 4;          // 0..15
    const int r0 = rb * 8;
    const int k0 = kb * 4;
    u64 acc[8][2];
    #pragma unroll
    for (int u = 0; u < 8; u++) { acc[u][0] = 0ull; acc[u][1] = 0ull; }

    const unsigned ax = xb + (unsigned)(r0 * XS_LD) * 4u;
    const unsigned bx = mb + (unsigned)k0 * 4u;

    #pragma unroll 4
    for (int i = 0; i < NIN; i += 2) {
        float2 av[8];
        #pragma unroll
        for (int u = 0; u < 8; u++)
            av[u] = lds_v2f(ax + (unsigned)(u * XS_LD + i) * 4u);
        u64 bp0, bp1, cp0, cp1;
        lds_v2u(bp0, bp1, bx + (unsigned)(i * NOUT) * 4u);
        lds_v2u(cp0, cp1, bx + (unsigned)((i + 1) * NOUT) * 4u);
        #pragma unroll
        for (int u = 0; u < 8; u++) {
            u64 a0 = dup2(av[u].x), a1 = dup2(av[u].y);
            fma2(acc[u][0], a0, bp0);
            fma2(acc[u][1], a0, bp1);
            fma2(acc[u][0], a1, cp0);
            fma2(acc[u][1], a1, cp1);
        }
    }

    // All GEMM1 reads of m_s must complete before w_s (alias) is written.
    __syncthreads();

    // ======== d-transform + softmax over k (16-lane xor shuffles) ========
    float mnl[4], ssl[4];
    #pragma unroll
    for (int q = 0; q < 4; q++) { mnl[q] = mn[k0 + q]; ssl[q] = s_s[k0 + q]; }

    #pragma unroll
    for (int u = 0; u < 8; u++) {
        const int r = r0 + u;
        const float xr = xn[r];
        float dv[4];
        float2 p0 = unpack2(acc[u][0]);
        float2 p1 = unpack2(acc[u][1]);
        dv[0] = ssl[0] * (xr - 2.f * p0.x + mnl[0]);
        dv[1] = ssl[1] * (xr - 2.f * p0.y + mnl[1]);
        dv[2] = ssl[2] * (xr - 2.f * p1.x + mnl[2]);
        dv[3] = ssl[3] * (xr - 2.f * p1.y + mnl[3]);

        float mx = fmaxf(fmaxf(dv[0], dv[1]), fmaxf(dv[2], dv[3]));
        #pragma unroll
        for (int off = 1; off < 16; off <<= 1)
            mx = fmaxf(mx, __shfl_xor_sync(0xffffffffu, mx, off));

        float ev[4], sum = 0.f;
        #pragma unroll
        for (int q = 0; q < 4; q++) { ev[q] = __expf(dv[q] - mx); sum += ev[q]; }
        #pragma unroll
        for (int off = 1; off < 16; off <<= 1)
            sum += __shfl_xor_sync(0xffffffffu, sum, off);

        const float inv = 1.f / sum;
        *reinterpret_cast<float4*>(w_s + r * WS_LD + k0) =
            make_float4(ev[0]*inv, ev[1]*inv, ev[2]*inv, ev[3]*inv);
    }
    __syncthreads();

    // ======== GEMM2: E[k][i] = sum_r w[r][k]*x[r][i], i-paired accs ========
    const int ib = tid >> 4;          // i = ib*8 .. ib*8+7
    const int i0 = ib * 8;
    u64 acc2[4][4];                   // [kq][p]; pair = (i0+2p, i0+2p+1)
    #pragma unroll
    for (int kq = 0; kq < 4; kq++)
        #pragma unroll
        for (int p = 0; p < 4; p++) acc2[kq][p] = 0ull;

    const unsigned xi = xb + (unsigned)i0 * 4u;
    const float* wrow = w_s + k0;

    #pragma unroll 8
    for (int r = 0; r < TILE_T; r++) {
        float4 wv = *reinterpret_cast<const float4*>(wrow + r * WS_LD);
        u64 xp[4];
        lds_v2u(xp[0], xp[1], xi + (unsigned)(r * XS_LD) * 4u);
        lds_v2u(xp[2], xp[3], xi + (unsigned)(r * XS_LD) * 4u + 16u);
        u64 w0 = dup2(wv.x), w1 = dup2(wv.y), w2 = dup2(wv.z), w3 = dup2(wv.w);
        #pragma unroll
        for (int p = 0; p < 4; p++) {
            fma2(acc2[0][p], w0, xp[p]);
            fma2(acc2[1][p], w1, xp[p]);
            fma2(acc2[2][p], w2, xp[p]);
            fma2(acc2[3][p], w3, xp[p]);
        }
    }

    // partE [b][c][k][i]: 16B stores, i-contiguous
    float* pe = g_partE + (size_t)(b * CHUNKS + c) * NOUT * NIN;
    #pragma unroll
    for (int kq = 0; kq < 4; kq++) {
        ulonglong2 o0; o0.x = acc2[kq][0]; o0.y = acc2[kq][1];
        ulonglong2 o1; o1.x = acc2[kq][2]; o1.y = acc2[kq][3];
        *reinterpret_cast<ulonglong2*>(pe + (k0 + kq) * NIN + i0)     = o0;
        *reinterpret_cast<ulonglong2*>(pe + (k0 + kq) * NIN + i0 + 4) = o1;
    }

    // ---- per-chunk wsum[k] ----
    if (tid < NOUT) {
        float a = 0.f;
        #pragma unroll 8
        for (int r = 0; r < TILE_T; r++) a += w_s[r * WS_LD + tid];
        g_partWS[(b * CHUNKS + c) * NOUT + tid] = a;
    }
}

__global__ __launch_bounds__(256) void lde_phase2(
    const float* __restrict__ m, float* __restrict__ out)
{
    const int g = blockIdx.x * 256 + threadIdx.x;   // 65536 = B*NOUT*(NIN/2)
    const int b = g >> 12;
    const int k = (g >> 6) & 63;
    const int p = g & 63;                           // i pair: i = 2p, 2p+1

    float2 se = make_float2(0.f, 0.f);
    float  sw = 0.f;
    #pragma unroll
    for (int c = 0; c < CHUNKS; c++) {
        const float2 v = *reinterpret_cast<const float2*>(
            g_partE + ((size_t)((b * CHUNKS + c) * NOUT + k)) * NIN + 2 * p);
        se.x += v.x; se.y += v.y;
        sw   += g_partWS[(b * CHUNKS + c) * NOUT + k];
    }
    const float m0 = m[(2 * p) * NOUT + k];
    const float m1 = m[(2 * p + 1) * NOUT + k];
    const float inv_t = 1.f / (float)T_;
    float2 o;
    o.x = (se.x - m0 * sw) * inv_t;
    o.y = (se.y - m1 * sw) * inv_t;
    *reinterpret_cast<float2*>(out + ((size_t)b * NOUT + k) * NIN + 2 * p) = o;
}

extern "C" void kernel_launch(void* const* d_in, const int* in_sizes, int n_in,
                              void* d_out, int out_size)
{
    const float* x = nullptr; const float* s = nullptr; const float* m = nullptr;
    for (int i = 0; i < n_in; i++) {
        if      (in_sizes[i] == B_ * T_ * NIN) x = (const float*)d_in[i];
        else if (in_sizes[i] == NOUT)          s = (const float*)d_in[i];
        else if (in_sizes[i] == NIN * NOUT)    m = (const float*)d_in[i];
    }
    float* out = (float*)d_out;

    const int smem_bytes =
        (TILE_T * XS_LD + TILE_T * WS_LD + TILE_T + 2 * NOUT)
        * (int)sizeof(float);   // ~104 KB

    cudaFuncSetAttribute(lde_phase1,
                         cudaFuncAttributeMaxDynamicSharedMemorySize, smem_bytes);

    lde_phase1<<<dim3(CHUNKS, B_), 256, smem_bytes>>>(x, s, m);
    lde_phase2<<<(B_ * NOUT * NIN / 2) / 256, 256>>>(m, out);
}